// round 3
// baseline (speedup 1.0000x reference)
#include <cuda_runtime.h>
#include <cuda_fp16.h>
#include <cstdint>

#define BATCH 8
#define CIN   128
#define COUT  128
#define RES   256
#define WDIM  512

// ---------------- device scratch (no allocations allowed) ----------------
__device__ float  g_styles[BATCH * CIN];
__device__ float  g_w2[COUT * CIN];
__device__ float  g_dcoef[BATCH * COUT];
// folded fp16 weights: [b][cc(4)][tap(9)][co(128)][ci32(32)]
__device__ __half g_wf[BATCH * 4 * 9 * COUT * 32];

// ---------------- prologue kernels ----------------
__global__ void k_styles(const float* __restrict__ w,
                         const float* __restrict__ aw,
                         const float* __restrict__ ab) {
    int b = blockIdx.x, i = threadIdx.x;
    float s = 0.f;
    const float* wr = w + b * WDIM;
    const float* ar = aw + i * WDIM;
    for (int d = 0; d < WDIM; d++) s += wr[d] * ar[d];
    g_styles[b * CIN + i] = s * 0.04419417382415922f /* 1/sqrt(512) */ + ab[i];
}

__global__ void k_w2(const float* __restrict__ wt) {
    int idx = blockIdx.x * blockDim.x + threadIdx.x;   // o*CIN + i
    if (idx >= COUT * CIN) return;
    const float* p = wt + idx * 9;
    float s = 0.f;
    #pragma unroll
    for (int t = 0; t < 9; t++) { float v = p[t]; s += v * v; }
    g_w2[idx] = s;
}

__global__ void k_dcoef() {
    int b = blockIdx.x, o = threadIdx.x;
    float s = 0.f;
    for (int i = 0; i < CIN; i++) {
        float st = g_styles[b * CIN + i];
        s += g_w2[o * CIN + i] * st * st;
    }
    g_dcoef[b * COUT + o] = rsqrtf(s + 1e-8f);
}

__global__ void k_fold(const float* __restrict__ wt) {
    int idx = blockIdx.x * blockDim.x + threadIdx.x;
    if (idx >= BATCH * 4 * 9 * COUT * 32) return;
    int ci32 = idx & 31;
    int co   = (idx >> 5) & 127;
    int tap  = (idx >> 12) % 9;
    int t2   = idx / (32 * 128 * 9);   // b*4 + cc
    int cc   = t2 & 3;
    int b    = t2 >> 2;
    int ci   = cc * 32 + ci32;
    float v = wt[(co * CIN + ci) * 9 + tap] * g_styles[b * CIN + ci] * g_dcoef[b * COUT + co];
    g_wf[idx] = __float2half(v);
}

// ---------------- mma helpers ----------------
__device__ __forceinline__ uint32_t smem_u32(const void* p) {
    uint32_t a;
    asm("{ .reg .u64 t; cvta.to.shared.u64 t, %1; cvt.u32.u64 %0, t; }" : "=r"(a) : "l"(p));
    return a;
}
__device__ __forceinline__ void ldsm_x4(uint32_t* r, uint32_t addr) {
    asm volatile("ldmatrix.sync.aligned.m8n8.x4.shared.b16 {%0,%1,%2,%3}, [%4];"
                 : "=r"(r[0]), "=r"(r[1]), "=r"(r[2]), "=r"(r[3]) : "r"(addr));
}
__device__ __forceinline__ void mma16816(float* c, const uint32_t* a, const uint32_t* b) {
    asm volatile(
        "mma.sync.aligned.m16n8k16.row.col.f32.f16.f16.f32 "
        "{%0,%1,%2,%3},{%4,%5,%6,%7},{%8,%9},{%0,%1,%2,%3};"
        : "+f"(c[0]), "+f"(c[1]), "+f"(c[2]), "+f"(c[3])
        : "r"(a[0]), "r"(a[1]), "r"(a[2]), "r"(a[3]), "r"(b[0]), "r"(b[1]));
}

// ---------------- smem layout ----------------
// s_in : half [3][130][40]  (kh, col, ci-padded-to-40)  -> 31,200 B
// s_w  : half [9*128][40]   (tap*128+co rows, 32 halfs + pad) -> 92,160 B at offset 31,232
// s_epi: float[128][132] overlaid at offset 0 (epilogue only) -> 67,584 B
#define IN_CSTR   40
#define W_OFF_B   31232
#define SMEM_BYTES (W_OFF_B + 9 * 128 * 40 * 2)   // 123,392

__global__ __launch_bounds__(256, 1)
void k_conv(const float* __restrict__ x,
            const float* __restrict__ noise,
            const float* __restrict__ nstr,
            const float* __restrict__ bias,
            float* __restrict__ out) {
    extern __shared__ char smem[];
    __half* s_in  = (__half*)smem;
    __half* s_w   = (__half*)(smem + W_OFF_B);
    float*  s_epi = (float*)smem;

    const int w0  = blockIdx.x * 128;   // 0 or 128
    const int h   = blockIdx.y;         // 0..255
    const int b   = blockIdx.z;         // 0..7
    const int tid = threadIdx.x;
    const int warp = tid >> 5, lane = tid & 31;
    const int wm = warp >> 1;   // pixel group 0..3  (32 pixels each)
    const int wn = warp & 1;    // cout  group 0..1  (64 couts each)

    float acc[2][8][4];
    #pragma unroll
    for (int a = 0; a < 2; a++)
        #pragma unroll
        for (int j = 0; j < 8; j++)
            #pragma unroll
            for (int c = 0; c < 4; c++) acc[a][j][c] = 0.f;

    const __half* wf_b = g_wf + (size_t)b * (4 * 9 * COUT * 32);
    const uint32_t s_in_u  = smem_u32(s_in);
    const uint32_t s_w_u   = smem_u32(s_w);

    #pragma unroll 1
    for (int cc = 0; cc < 4; cc++) {
        __syncthreads();   // previous iter done reading smem

        // ---- load folded weight chunk: 9*128 rows of 64B ----
        {
            const uint4* src = (const uint4*)(wf_b + (size_t)cc * 9 * 128 * 32);
            #pragma unroll 1
            for (int i = tid; i < 4608; i += 256) {
                int row = i >> 2;
                int col = i & 3;
                uint4 v = src[i];
                *((uint4*)(s_w + row * 40 + col * 8)) = v;
            }
        }
        // ---- load input chunk: 32 ci x 3 rows x 130 cols, fp32 -> fp16, transposed ----
        {
            int ci0 = cc * 32;
            #pragma unroll 1
            for (int i = tid; i < 6240; i += 256) {
                int c  = i % 130;
                int kh = (i / 130) % 3;
                int cp = i / 390;              // ci pair 0..15
                int ci = ci0 + cp * 2;
                int gr = h + kh - 1;
                int gc = w0 + c - 1;
                float v0 = 0.f, v1 = 0.f;
                if ((unsigned)gr < RES && (unsigned)gc < RES) {
                    const float* xp = x + (((size_t)(b * CIN + ci)) * RES + gr) * RES + gc;
                    v0 = xp[0];
                    v1 = xp[(size_t)RES * RES];
                }
                *((__half2*)(s_in + (kh * 130 + c) * IN_CSTR + cp * 2)) = __floats2half2_rn(v0, v1);
            }
        }
        __syncthreads();

        // ---- compute: 9 taps x 2 k16 steps ----
        #pragma unroll
        for (int tap = 0; tap < 9; tap++) {
            const int kh = tap / 3, kw = tap % 3;
            const uint32_t a_row0 = s_in_u + (uint32_t)((kh * 130 + kw) * IN_CSTR) * 2;
            const uint32_t b_row0 = s_w_u  + (uint32_t)(tap * 128 * 40) * 2;
            #pragma unroll
            for (int ks = 0; ks < 2; ks++) {
                const int k0 = ks * 16;
                uint32_t afrag[2][4];
                #pragma unroll
                for (int mi = 0; mi < 2; mi++) {
                    int row = wm * 32 + mi * 16 + (lane & 15);
                    uint32_t addr = a_row0 + (uint32_t)(row * IN_CSTR + k0 + ((lane >> 4) << 3)) * 2;
                    ldsm_x4(afrag[mi], addr);
                }
                // B fragment: s_w tile is [cout][k] row-major -> NON-trans ldmatrix
                // yields exactly the mma.col B fragment (n = t/4, k = (t%4)*2+e).
                uint32_t bfrag[4][4];
                #pragma unroll
                for (int ni = 0; ni < 4; ni++) {
                    int row = wn * 64 + ni * 16 + (lane & 7) + ((lane >> 4) << 3);
                    uint32_t addr = b_row0 + (uint32_t)(row * 40 + k0 + (((lane >> 3) & 1) << 3)) * 2;
                    ldsm_x4(bfrag[ni], addr);
                }
                #pragma unroll
                for (int mi = 0; mi < 2; mi++)
                    #pragma unroll
                    for (int ni = 0; ni < 4; ni++) {
                        mma16816(acc[mi][ni * 2],     afrag[mi], bfrag[ni]);
                        mma16816(acc[mi][ni * 2 + 1], afrag[mi], bfrag[ni] + 2);
                    }
            }
        }
    }

    // ---------------- epilogue ----------------
    const float ns = nstr[0];
    const float* nrow = noise + (size_t)h * RES + w0;
    __syncthreads();   // everyone done reading s_in/s_w before overlaying s_epi

    const float SQ2 = 1.4142135623730951f;
    #pragma unroll
    for (int mi = 0; mi < 2; mi++) {
        int p0 = wm * 32 + mi * 16 + (lane >> 2);
        float nv0 = nrow[p0] * ns;
        float nv1 = nrow[p0 + 8] * ns;
        #pragma unroll
        for (int j = 0; j < 8; j++) {
            int co0 = wn * 64 + j * 8 + (lane & 3) * 2;
            float b0 = bias[co0], b1 = bias[co0 + 1];
            float* a = acc[mi][j];
            float v;
            v = a[0] + nv0 + b0; v = (v >= 0.f) ? v : 0.2f * v; v *= SQ2;
            s_epi[co0 * 132 + p0] = fminf(fmaxf(v, -256.f), 256.f);
            v = a[1] + nv0 + b1; v = (v >= 0.f) ? v : 0.2f * v; v *= SQ2;
            s_epi[(co0 + 1) * 132 + p0] = fminf(fmaxf(v, -256.f), 256.f);
            v = a[2] + nv1 + b0; v = (v >= 0.f) ? v : 0.2f * v; v *= SQ2;
            s_epi[co0 * 132 + p0 + 8] = fminf(fmaxf(v, -256.f), 256.f);
            v = a[3] + nv1 + b1; v = (v >= 0.f) ? v : 0.2f * v; v *= SQ2;
            s_epi[(co0 + 1) * 132 + p0 + 8] = fminf(fmaxf(v, -256.f), 256.f);
        }
    }
    __syncthreads();

    // coalesced writeout: 2 threads per cout row, 64 floats each
    {
        int co  = tid >> 1;
        int off = (tid & 1) * 64;
        float* dst = out + (((size_t)(b * COUT + co)) * RES + h) * RES + w0 + off;
        const float* sp = s_epi + co * 132 + off;
        #pragma unroll
        for (int q = 0; q < 64; q += 4)
            *((float4*)(dst + q)) = *((const float4*)(sp + q));
    }
}

// ---------------- launch ----------------
extern "C" void kernel_launch(void* const* d_in, const int* in_sizes, int n_in,
                              void* d_out, int out_size) {
    const float* x     = (const float*)d_in[0];
    const float* w     = (const float*)d_in[1];
    const float* aw    = (const float*)d_in[2];
    const float* ab    = (const float*)d_in[3];
    const float* wt    = (const float*)d_in[4];
    const float* noise = (const float*)d_in[5];
    const float* nstr  = (const float*)d_in[6];
    const float* bias  = (const float*)d_in[7];
    float* out = (float*)d_out;

    k_styles<<<BATCH, CIN>>>(w, aw, ab);
    k_w2<<<(COUT * CIN + 255) / 256, 256>>>(wt);
    k_dcoef<<<BATCH, COUT>>>();
    k_fold<<<(BATCH * 4 * 9 * COUT * 32) / 256, 256>>>(wt);

    cudaFuncSetAttribute(k_conv, cudaFuncAttributeMaxDynamicSharedMemorySize, SMEM_BYTES);
    dim3 grid(2, RES, BATCH);
    k_conv<<<grid, 256, SMEM_BYTES>>>(x, noise, nstr, bias, out);
}

// round 4
// speedup vs baseline: 2.4207x; 2.4207x over previous
#include <cuda_runtime.h>
#include <cuda_fp16.h>
#include <cstdint>

#define BATCH 8
#define CIN   128
#define COUT  128
#define RES   256
#define WDIM  512
#define CH    16      // ci per chunk
#define NCH   8       // chunks

// ---------------- device scratch ----------------
__device__ float  g_styles[BATCH * CIN];
__device__ float  g_w2[COUT * CIN];
__device__ float  g_dcoef[BATCH * COUT];
// folded fp16 weights: [b][cc(8)][tap(9)][co(128)][ci16(16)]
__device__ __half g_wf[BATCH * NCH * 9 * COUT * CH];
// fp16 NHWC input: [b][h][w][ci]
__device__ __half g_xh[(size_t)BATCH * RES * RES * CIN];

// ---------------- prologue kernels ----------------
__global__ void k_styles(const float* __restrict__ w,
                         const float* __restrict__ aw,
                         const float* __restrict__ ab) {
    int b = blockIdx.x, i = threadIdx.x;
    float s = 0.f;
    const float* wr = w + b * WDIM;
    const float* ar = aw + i * WDIM;
    for (int d = 0; d < WDIM; d++) s += wr[d] * ar[d];
    g_styles[b * CIN + i] = s * 0.04419417382415922f + ab[i];
}

__global__ void k_w2(const float* __restrict__ wt) {
    int idx = blockIdx.x * blockDim.x + threadIdx.x;
    if (idx >= COUT * CIN) return;
    const float* p = wt + idx * 9;
    float s = 0.f;
    #pragma unroll
    for (int t = 0; t < 9; t++) { float v = p[t]; s += v * v; }
    g_w2[idx] = s;
}

__global__ void k_dcoef() {
    int b = blockIdx.x, o = threadIdx.x;
    float s = 0.f;
    for (int i = 0; i < CIN; i++) {
        float st = g_styles[b * CIN + i];
        s += g_w2[o * CIN + i] * st * st;
    }
    g_dcoef[b * COUT + o] = rsqrtf(s + 1e-8f);
}

__global__ void k_fold(const float* __restrict__ wt) {
    int idx = blockIdx.x * blockDim.x + threadIdx.x;
    if (idx >= BATCH * NCH * 9 * COUT * CH) return;
    int ci16 = idx & 15;
    int co   = (idx >> 4) & 127;
    int rest = idx >> 11;
    int tap  = rest % 9;
    int bcc  = rest / 9;
    int cc   = bcc & 7;
    int b    = bcc >> 3;
    int ci   = cc * CH + ci16;
    float v = wt[(co * CIN + ci) * 9 + tap] * g_styles[b * CIN + ci] * g_dcoef[b * COUT + co];
    g_wf[idx] = __float2half(v);
}

// NCHW fp32 -> NHWC fp16 transpose-convert. Block: (ci 128 x w 32) for one (b,h).
__global__ __launch_bounds__(256, 1) void k_half(const float* __restrict__ x) {
    __shared__ float s[32][132];   // [w][ci]
    int b = blockIdx.z, h = blockIdx.y, w0 = blockIdx.x * 32;
    int tid = threadIdx.x;
    {
        int ci = tid >> 1, wseg = (tid & 1) * 16;
        const float* src = x + (((size_t)(b * CIN + ci) * RES + h) * RES + w0 + wseg);
        #pragma unroll
        for (int j = 0; j < 4; j++) {
            float4 v = *((const float4*)(src + j * 4));
            s[wseg + j * 4 + 0][ci] = v.x;
            s[wseg + j * 4 + 1][ci] = v.y;
            s[wseg + j * 4 + 2][ci] = v.z;
            s[wseg + j * 4 + 3][ci] = v.w;
        }
    }
    __syncthreads();
    {
        int wl = tid >> 3, c0 = (tid & 7) * 16;
        __half hv[16];
        #pragma unroll
        for (int j = 0; j < 4; j++) {
            float4 v = *((const float4*)(&s[wl][c0 + j * 4]));
            hv[j * 4 + 0] = __float2half(v.x);
            hv[j * 4 + 1] = __float2half(v.y);
            hv[j * 4 + 2] = __float2half(v.z);
            hv[j * 4 + 3] = __float2half(v.w);
        }
        __half* dst = g_xh + (((size_t)(b * RES + h) * RES + w0 + wl) * CIN + c0);
        *((uint4*)dst)       = *((uint4*)hv);
        *((uint4*)(dst + 8)) = *((uint4*)(hv + 8));
    }
}

// ---------------- mma helpers ----------------
__device__ __forceinline__ uint32_t smem_u32(const void* p) {
    uint32_t a;
    asm("{ .reg .u64 t; cvta.to.shared.u64 t, %1; cvt.u32.u64 %0, t; }" : "=r"(a) : "l"(p));
    return a;
}
__device__ __forceinline__ void ldsm_x4(uint32_t* r, uint32_t addr) {
    asm volatile("ldmatrix.sync.aligned.m8n8.x4.shared.b16 {%0,%1,%2,%3}, [%4];"
                 : "=r"(r[0]), "=r"(r[1]), "=r"(r[2]), "=r"(r[3]) : "r"(addr));
}
__device__ __forceinline__ void mma16816(float* c, const uint32_t* a, uint32_t b0, uint32_t b1) {
    asm volatile(
        "mma.sync.aligned.m16n8k16.row.col.f32.f16.f16.f32 "
        "{%0,%1,%2,%3},{%4,%5,%6,%7},{%8,%9},{%0,%1,%2,%3};"
        : "+f"(c[0]), "+f"(c[1]), "+f"(c[2]), "+f"(c[3])
        : "r"(a[0]), "r"(a[1]), "r"(a[2]), "r"(a[3]), "r"(b0), "r"(b1));
}
__device__ __forceinline__ void cpa16(uint32_t dst, const void* src, int sz) {
    asm volatile("cp.async.cg.shared.global [%0], [%1], 16, %2;\n"
                 :: "r"(dst), "l"(src), "r"(sz));
}
__device__ __forceinline__ void cpa_commit() { asm volatile("cp.async.commit_group;\n"); }

// ---------------- conv smem layout ----------------
// input  buf: 390 rows (kh*130+c) x 16 halves, stride 24 halves (48 B) -> 18,720 B each
// weight buf: 1152 rows (tap*128+co) x 16 halves, stride 24 halves    -> 55,296 B each
// [in0][in1][w0][w1] = 2*18720 + 2*55296 = 148,032 B
// s_epi float[128][132] = 67,584 B overlays for epilogue
#define IN_BUF_B  18720
#define W_BUF_B   55296
#define W_OFF_B   37440
#define SMEM_BYTES 148032

__device__ __forceinline__ void issue_chunk(
    int cc, int buf, int tid, int h, int w0,
    uint32_t s_in_u, uint32_t s_w_u,
    const __half* __restrict__ xh_b, const __half* __restrict__ wf_b)
{
    // weights: chunk is contiguous 36,864 B = 2304 x 16B segs; 9 per thread
    const __half* wsrc = wf_b + (size_t)cc * (9 * COUT * CH);
    uint32_t wdst = s_w_u + buf * W_BUF_B;
    #pragma unroll
    for (int j = 0; j < 9; j++) {
        int i = tid + j * 256;            // 0..2303
        int row = i >> 1, seg = i & 1;
        cpa16(wdst + row * 48 + seg * 16, wsrc + i * 8, 16);
    }
    // input: 390 rows x 2 segs = 780 x 16B
    uint32_t idst = s_in_u + buf * IN_BUF_B;
    #pragma unroll
    for (int j = 0; j < 4; j++) {
        int i = tid + j * 256;
        if (i < 780) {
            int row = i >> 1, seg = i & 1;
            int kh = row / 130;
            int c  = row - kh * 130;
            int gr = h + kh - 1, gc = w0 + c - 1;
            bool ok = ((unsigned)gr < RES) && ((unsigned)gc < RES);
            const __half* src = ok
                ? (xh_b + (((size_t)gr * RES + gc) * CIN + cc * CH + seg * 8))
                : xh_b;
            cpa16(idst + row * 48 + seg * 16, src, ok ? 16 : 0);
        }
    }
}

__global__ __launch_bounds__(256, 1)
void k_conv(const float* __restrict__ noise,
            const float* __restrict__ nstr,
            const float* __restrict__ bias,
            float* __restrict__ out) {
    extern __shared__ char smem[];
    float* s_epi = (float*)smem;

    const int w0  = blockIdx.x * 128;
    const int h   = blockIdx.y;
    const int b   = blockIdx.z;
    const int tid = threadIdx.x;
    const int warp = tid >> 5, lane = tid & 31;
    const int wm = warp >> 1;   // pixel group 0..3 (32 pixels each)
    const int wn = warp & 1;    // cout  group 0..1 (64 couts each)

    const uint32_t s_in_u = smem_u32(smem);
    const uint32_t s_w_u  = s_in_u + W_OFF_B;
    const __half* xh_b = g_xh + (size_t)b * RES * RES * CIN;
    const __half* wf_b = g_wf + (size_t)b * (NCH * 9 * COUT * CH);

    float acc[2][8][4];
    #pragma unroll
    for (int a = 0; a < 2; a++)
        #pragma unroll
        for (int j = 0; j < 8; j++)
            #pragma unroll
            for (int c = 0; c < 4; c++) acc[a][j][c] = 0.f;

    issue_chunk(0, 0, tid, h, w0, s_in_u, s_w_u, xh_b, wf_b);
    cpa_commit();

    // per-lane ldmatrix bases (byte addresses)
    const uint32_t a_lane = s_in_u + (wm * 32 + (lane & 15)) * 48 + ((lane >> 4) << 4);
    const uint32_t b_lane = s_w_u  + (wn * 64 + (lane & 15)) * 48 + ((lane >> 4) << 4);

    #pragma unroll 1
    for (int cc = 0; cc < NCH; cc++) {
        if (cc < NCH - 1) {
            issue_chunk(cc + 1, (cc + 1) & 1, tid, h, w0, s_in_u, s_w_u, xh_b, wf_b);
            cpa_commit();
            asm volatile("cp.async.wait_group 1;\n");
        } else {
            asm volatile("cp.async.wait_group 0;\n");
        }
        __syncthreads();

        const uint32_t ab = a_lane + (cc & 1) * IN_BUF_B;
        const uint32_t bb = b_lane + (cc & 1) * W_BUF_B;
        #pragma unroll
        for (int tap = 0; tap < 9; tap++) {
            const int kh = tap / 3, kw = tap % 3;
            const uint32_t arow = ab + (uint32_t)(kh * 130 + kw) * 48;
            const uint32_t brow = bb + (uint32_t)tap * 6144;   // 128 rows * 48 B
            uint32_t af[2][4], bf[4][4];
            ldsm_x4(af[0], arow);
            ldsm_x4(af[1], arow + 768);                        // +16 rows
            #pragma unroll
            for (int ni = 0; ni < 4; ni++) ldsm_x4(bf[ni], brow + ni * 768);
            #pragma unroll
            for (int mi = 0; mi < 2; mi++)
                #pragma unroll
                for (int ni = 0; ni < 4; ni++) {
                    // co(0-7) of tile: regs {0,2}; co(8-15): regs {1,3}
                    mma16816(acc[mi][ni * 2],     af[mi], bf[ni][0], bf[ni][2]);
                    mma16816(acc[mi][ni * 2 + 1], af[mi], bf[ni][1], bf[ni][3]);
                }
        }
        __syncthreads();
    }

    // ---------------- epilogue (verified in R2) ----------------
    const float ns = nstr[0];
    const float* nrow = noise + (size_t)h * RES + w0;
    const float SQ2 = 1.4142135623730951f;
    #pragma unroll
    for (int mi = 0; mi < 2; mi++) {
        int p0 = wm * 32 + mi * 16 + (lane >> 2);
        float nv0 = nrow[p0] * ns;
        float nv1 = nrow[p0 + 8] * ns;
        #pragma unroll
        for (int j = 0; j < 8; j++) {
            int co0 = wn * 64 + j * 8 + (lane & 3) * 2;
            float b0 = bias[co0], b1 = bias[co0 + 1];
            float* a = acc[mi][j];
            float v;
            v = a[0] + nv0 + b0; v = (v >= 0.f) ? v : 0.2f * v; v *= SQ2;
            s_epi[co0 * 132 + p0] = fminf(fmaxf(v, -256.f), 256.f);
            v = a[1] + nv0 + b1; v = (v >= 0.f) ? v : 0.2f * v; v *= SQ2;
            s_epi[(co0 + 1) * 132 + p0] = fminf(fmaxf(v, -256.f), 256.f);
            v = a[2] + nv1 + b0; v = (v >= 0.f) ? v : 0.2f * v; v *= SQ2;
            s_epi[co0 * 132 + p0 + 8] = fminf(fmaxf(v, -256.f), 256.f);
            v = a[3] + nv1 + b1; v = (v >= 0.f) ? v : 0.2f * v; v *= SQ2;
            s_epi[(co0 + 1) * 132 + p0 + 8] = fminf(fmaxf(v, -256.f), 256.f);
        }
    }
    __syncthreads();

    {
        int co  = tid >> 1;
        int off = (tid & 1) * 64;
        float* dst = out + (((size_t)(b * COUT + co)) * RES + h) * RES + w0 + off;
        const float* sp = s_epi + co * 132 + off;
        #pragma unroll
        for (int q = 0; q < 64; q += 4)
            *((float4*)(dst + q)) = *((const float4*)(sp + q));
    }
}

// ---------------- launch ----------------
extern "C" void kernel_launch(void* const* d_in, const int* in_sizes, int n_in,
                              void* d_out, int out_size) {
    const float* x     = (const float*)d_in[0];
    const float* w     = (const float*)d_in[1];
    const float* aw    = (const float*)d_in[2];
    const float* ab    = (const float*)d_in[3];
    const float* wt    = (const float*)d_in[4];
    const float* noise = (const float*)d_in[5];
    const float* nstr  = (const float*)d_in[6];
    const float* bias  = (const float*)d_in[7];
    float* out = (float*)d_out;

    k_styles<<<BATCH, CIN>>>(w, aw, ab);
    k_w2<<<(COUT * CIN + 255) / 256, 256>>>(wt);
    k_dcoef<<<BATCH, COUT>>>();
    k_fold<<<(BATCH * NCH * 9 * COUT * CH + 255) / 256, 256>>>(wt);

    dim3 hgrid(RES / 32, RES, BATCH);
    k_half<<<hgrid, 256>>>(x);

    cudaFuncSetAttribute(k_conv, cudaFuncAttributeMaxDynamicSharedMemorySize, SMEM_BYTES);
    dim3 grid(2, RES, BATCH);
    k_conv<<<grid, 256, SMEM_BYTES>>>(noise, nstr, bias, out);
}

// round 6
// speedup vs baseline: 2.6575x; 1.0978x over previous
#include <cuda_runtime.h>
#include <cuda_fp16.h>
#include <cstdint>

#define BATCH 8
#define CIN   128
#define COUT  128
#define RES   256
#define WDIM  512
#define CH    16      // ci per chunk
#define NCH   8       // chunks

// ---------------- device scratch ----------------
__device__ float  g_styles[BATCH * CIN];
__device__ float  g_w2[COUT * CIN];
__device__ float  g_dcoef[BATCH * COUT];
// folded fp16 weights: [b][cc(8)][tap(9)][co(128)][ci16(16)]
__device__ __half g_wf[BATCH * NCH * 9 * COUT * CH];
// fp16 chunked-NHWC input: [b][cc(8)][h][w][ci16(16)]
__device__ __half g_xh[(size_t)BATCH * NCH * RES * RES * CH];

// ---------------- prologue kernels ----------------
__global__ void k_styles(const float* __restrict__ w,
                         const float* __restrict__ aw,
                         const float* __restrict__ ab) {
    int b = blockIdx.x, i = threadIdx.x;
    float s = 0.f;
    const float* wr = w + b * WDIM;
    const float* ar = aw + i * WDIM;
    for (int d = 0; d < WDIM; d++) s += wr[d] * ar[d];
    g_styles[b * CIN + i] = s * 0.04419417382415922f + ab[i];
}

__global__ void k_w2(const float* __restrict__ wt) {
    int idx = blockIdx.x * blockDim.x + threadIdx.x;
    if (idx >= COUT * CIN) return;
    const float* p = wt + idx * 9;
    float s = 0.f;
    #pragma unroll
    for (int t = 0; t < 9; t++) { float v = p[t]; s += v * v; }
    g_w2[idx] = s;
}

__global__ void k_dcoef() {
    int b = blockIdx.x, o = threadIdx.x;
    float s = 0.f;
    for (int i = 0; i < CIN; i++) {
        float st = g_styles[b * CIN + i];
        s += g_w2[o * CIN + i] * st * st;
    }
    g_dcoef[b * COUT + o] = rsqrtf(s + 1e-8f);
}

__global__ void k_fold(const float* __restrict__ wt) {
    int idx = blockIdx.x * blockDim.x + threadIdx.x;
    if (idx >= BATCH * NCH * 9 * COUT * CH) return;
    int ci16 = idx & 15;
    int co   = (idx >> 4) & 127;
    int rest = idx >> 11;
    int tap  = rest % 9;
    int bcc  = rest / 9;
    int cc   = bcc & 7;
    int b    = bcc >> 3;
    int ci   = cc * CH + ci16;
    float v = wt[(co * CIN + ci) * 9 + tap] * g_styles[b * CIN + ci] * g_dcoef[b * COUT + co];
    g_wf[idx] = __float2half(v);
}

// NCHW fp32 -> chunked NHWC fp16. Block: (ci 128 x w 32) for one (b,h).
__global__ __launch_bounds__(256, 1) void k_half(const float* __restrict__ x) {
    __shared__ float s[32][132];   // [w][ci]
    int b = blockIdx.z, h = blockIdx.y, w0 = blockIdx.x * 32;
    int tid = threadIdx.x;
    {
        int ci = tid >> 1, wseg = (tid & 1) * 16;
        const float* src = x + (((size_t)(b * CIN + ci) * RES + h) * RES + w0 + wseg);
        #pragma unroll
        for (int j = 0; j < 4; j++) {
            float4 v = *((const float4*)(src + j * 4));
            s[wseg + j * 4 + 0][ci] = v.x;
            s[wseg + j * 4 + 1][ci] = v.y;
            s[wseg + j * 4 + 2][ci] = v.z;
            s[wseg + j * 4 + 3][ci] = v.w;
        }
    }
    __syncthreads();
    {
        int wl = tid >> 3, cc = tid & 7;
        __half hv[16];
        #pragma unroll
        for (int j = 0; j < 4; j++) {
            float4 v = *((const float4*)(&s[wl][cc * 16 + j * 4]));
            hv[j * 4 + 0] = __float2half(v.x);
            hv[j * 4 + 1] = __float2half(v.y);
            hv[j * 4 + 2] = __float2half(v.z);
            hv[j * 4 + 3] = __float2half(v.w);
        }
        __half* dst = g_xh + ((((size_t)(b * NCH + cc) * RES + h) * RES + (w0 + wl)) * CH);
        *((uint4*)dst)       = *((uint4*)hv);
        *((uint4*)(dst + 8)) = *((uint4*)(hv + 8));
    }
}

// ---------------- mma helpers ----------------
__device__ __forceinline__ uint32_t smem_u32(const void* p) {
    uint32_t a;
    asm("{ .reg .u64 t; cvta.to.shared.u64 t, %1; cvt.u32.u64 %0, t; }" : "=r"(a) : "l"(p));
    return a;
}
__device__ __forceinline__ void ldsm_x4(uint32_t* r, uint32_t addr) {
    asm volatile("ldmatrix.sync.aligned.m8n8.x4.shared.b16 {%0,%1,%2,%3}, [%4];"
                 : "=r"(r[0]), "=r"(r[1]), "=r"(r[2]), "=r"(r[3]) : "r"(addr));
}
__device__ __forceinline__ void mma16816(float* c, const uint32_t* a, uint32_t b0, uint32_t b1) {
    asm volatile(
        "mma.sync.aligned.m16n8k16.row.col.f32.f16.f16.f32 "
        "{%0,%1,%2,%3},{%4,%5,%6,%7},{%8,%9},{%0,%1,%2,%3};"
        : "+f"(c[0]), "+f"(c[1]), "+f"(c[2]), "+f"(c[3])
        : "r"(a[0]), "r"(a[1]), "r"(a[2]), "r"(a[3]), "r"(b0), "r"(b1));
}
__device__ __forceinline__ void cpa16(uint32_t dst, const void* src, int sz) {
    asm volatile("cp.async.cg.shared.global [%0], [%1], 16, %2;\n"
                 :: "r"(dst), "l"(src), "r"(sz));
}
__device__ __forceinline__ void cpa_commit() { asm volatile("cp.async.commit_group;\n"); }

// ---------------- conv smem layout ----------------
// input  buf: 4 kh-rows x 130 cols x 16 halves, row stride 48 B -> 24,960 B each
// weight buf: 1152 rows (tap*128+co) x 16 halves, stride 48 B    -> 55,296 B each
// [in0][in1][w0][w1] = 2*24960 + 2*55296 = 160,512 B
// s_epi float[128][132] = 67,584 B overlays for epilogue
#define IN_BUF_B  24960
#define W_BUF_B   55296
#define W_OFF_B   49920
#define SMEM_BYTES 160512

__device__ __forceinline__ void issue_chunk(
    int cc, int buf, int tid, int h0, int w0,
    uint32_t s_in_u, uint32_t s_w_u,
    const __half* __restrict__ xh_b, const __half* __restrict__ wf_b)
{
    // weights: chunk is contiguous 36,864 B = 2304 x 16B segs; 9 per thread
    const __half* wsrc = wf_b + (size_t)cc * (9 * COUT * CH);
    uint32_t wdst = s_w_u + buf * W_BUF_B;
    #pragma unroll
    for (int j = 0; j < 9; j++) {
        int i = tid + j * 256;            // 0..2303
        int row = i >> 1, seg = i & 1;
        cpa16(wdst + row * 48 + seg * 16, wsrc + i * 8, 16);
    }
    // input: 4 rows x 130 cols x 2 segs = 1040 x 16B
    const __half* xh_cc = xh_b + (size_t)cc * (RES * RES * CH);
    uint32_t idst = s_in_u + buf * IN_BUF_B;
    #pragma unroll
    for (int j = 0; j < 5; j++) {
        int i = tid + j * 256;
        if (i < 1040) {
            int row = i >> 1, seg = i & 1;
            int kh = row / 130;
            int c  = row - kh * 130;
            int gr = h0 + kh - 1, gc = w0 + c - 1;
            bool ok = ((unsigned)gr < RES) && ((unsigned)gc < RES);
            const __half* src = ok
                ? (xh_cc + ((size_t)gr * RES + gc) * CH + seg * 8)
                : xh_cc;
            cpa16(idst + row * 48 + seg * 16, src, ok ? 16 : 0);
        }
    }
}

__global__ __launch_bounds__(256, 1)
void k_conv(const float* __restrict__ noise,
            const float* __restrict__ nstr,
            const float* __restrict__ bias,
            float* __restrict__ out) {
    extern __shared__ char smem[];
    float* s_epi = (float*)smem;

    const int w0  = blockIdx.x * 128;
    const int h0  = blockIdx.y * 2;     // two output rows per block
    const int b   = blockIdx.z;
    const int tid = threadIdx.x;
    const int warp = tid >> 5, lane = tid & 31;
    const int wm = warp >> 1;   // pixel group 0..3 (64 pixels each)
    const int wn = warp & 1;    // cout  group 0..1 (64 couts each)
    const int wr = wm >> 1;     // output row within block
    const int wc = wm & 1;      // column half (0: c 0-63, 1: c 64-127)

    const uint32_t s_in_u = smem_u32(smem);
    const uint32_t s_w_u  = s_in_u + W_OFF_B;
    const __half* xh_b = g_xh + (size_t)b * (NCH * RES * RES * CH);
    const __half* wf_b = g_wf + (size_t)b * (NCH * 9 * COUT * CH);

    float acc[4][8][4];
    #pragma unroll
    for (int a = 0; a < 4; a++)
        #pragma unroll
        for (int j = 0; j < 8; j++)
            #pragma unroll
            for (int c = 0; c < 4; c++) acc[a][j][c] = 0.f;

    issue_chunk(0, 0, tid, h0, w0, s_in_u, s_w_u, xh_b, wf_b);
    cpa_commit();

    // per-lane ldmatrix bases (byte addresses)
    // A row for (tap kh,kw; tile mi): (wr + kh)*130 + wc*64 + mi*16 + (lane&15) + kw
    const uint32_t a_lane = s_in_u + (uint32_t)((wr * 130 + wc * 64 + (lane & 15)) * 48 + ((lane >> 4) << 4));
    const uint32_t b_lane = s_w_u  + (uint32_t)((wn * 64 + (lane & 15)) * 48 + ((lane >> 4) << 4));

    #pragma unroll 1
    for (int cc = 0; cc < NCH; cc++) {
        if (cc < NCH - 1) {
            issue_chunk(cc + 1, (cc + 1) & 1, tid, h0, w0, s_in_u, s_w_u, xh_b, wf_b);
            cpa_commit();
            asm volatile("cp.async.wait_group 1;\n");
        } else {
            asm volatile("cp.async.wait_group 0;\n");
        }
        __syncthreads();

        const uint32_t ab = a_lane + (cc & 1) * IN_BUF_B;
        const uint32_t bb = b_lane + (cc & 1) * W_BUF_B;
        #pragma unroll
        for (int tap = 0; tap < 9; tap++) {
            const int kh = tap / 3, kw = tap % 3;
            const uint32_t arow = ab + (uint32_t)(kh * 130 + kw) * 48;
            const uint32_t brow = bb + (uint32_t)tap * 6144;   // 128 rows * 48 B
            uint32_t af[4][4], bf[4][4];
            #pragma unroll
            for (int mi = 0; mi < 4; mi++) ldsm_x4(af[mi], arow + mi * 768);   // +16 rows
            #pragma unroll
            for (int ni = 0; ni < 4; ni++) ldsm_x4(bf[ni], brow + ni * 768);
            #pragma unroll
            for (int mi = 0; mi < 4; mi++)
                #pragma unroll
                for (int ni = 0; ni < 4; ni++) {
                    mma16816(acc[mi][ni * 2],     af[mi], bf[ni][0], bf[ni][2]);
                    mma16816(acc[mi][ni * 2 + 1], af[mi], bf[ni][1], bf[ni][3]);
                }
        }
        __syncthreads();
    }

    // ---------------- epilogue: two passes (one per output row) ----------------
    const float ns = nstr[0];
    const float SQ2 = 1.4142135623730951f;

    #pragma unroll 1
    for (int r = 0; r < 2; r++) {
        if (wr == r) {
            const float* nrow = noise + (size_t)(h0 + r) * RES + w0;
            #pragma unroll
            for (int mi = 0; mi < 4; mi++) {
                int p0 = wc * 64 + mi * 16 + (lane >> 2);
                float nv0 = nrow[p0] * ns;
                float nv1 = nrow[p0 + 8] * ns;
                #pragma unroll
                for (int j = 0; j < 8; j++) {
                    int co0 = wn * 64 + j * 8 + (lane & 3) * 2;
                    float b0 = bias[co0], b1 = bias[co0 + 1];
                    float* a = acc[mi][j];
                    float v;
                    v = a[0] + nv0 + b0; v = (v >= 0.f) ? v : 0.2f * v; v *= SQ2;
                    s_epi[co0 * 132 + p0] = fminf(fmaxf(v, -256.f), 256.f);
                    v = a[1] + nv0 + b1; v = (v >= 0.f) ? v : 0.2f * v; v *= SQ2;
                    s_epi[(co0 + 1) * 132 + p0] = fminf(fmaxf(v, -256.f), 256.f);
                    v = a[2] + nv1 + b0; v = (v >= 0.f) ? v : 0.2f * v; v *= SQ2;
                    s_epi[co0 * 132 + p0 + 8] = fminf(fmaxf(v, -256.f), 256.f);
                    v = a[3] + nv1 + b1; v = (v >= 0.f) ? v : 0.2f * v; v *= SQ2;
                    s_epi[(co0 + 1) * 132 + p0 + 8] = fminf(fmaxf(v, -256.f), 256.f);
                }
            }
        }
        __syncthreads();
        {
            int co  = tid >> 1;
            int off = (tid & 1) * 64;
            float* dst = out + (((size_t)(b * COUT + co)) * RES + (h0 + r)) * RES + w0 + off;
            const float* sp = s_epi + co * 132 + off;
            #pragma unroll
            for (int q = 0; q < 64; q += 4)
                *((float4*)(dst + q)) = *((const float4*)(sp + q));
        }
        __syncthreads();
    }
}

// ---------------- launch ----------------
extern "C" void kernel_launch(void* const* d_in, const int* in_sizes, int n_in,
                              void* d_out, int out_size) {
    const float* x     = (const float*)d_in[0];
    const float* w     = (const float*)d_in[1];
    const float* aw    = (const float*)d_in[2];
    const float* ab    = (const float*)d_in[3];
    const float* wt    = (const float*)d_in[4];
    const float* noise = (const float*)d_in[5];
    const float* nstr  = (const float*)d_in[6];
    const float* bias  = (const float*)d_in[7];
    float* out = (float*)d_out;

    k_styles<<<BATCH, CIN>>>(w, aw, ab);
    k_w2<<<(COUT * CIN + 255) / 256, 256>>>(wt);
    k_dcoef<<<BATCH, COUT>>>();
    k_fold<<<(BATCH * NCH * 9 * COUT * CH + 255) / 256, 256>>>(wt);

    dim3 hgrid(RES / 32, RES, BATCH);
    k_half<<<hgrid, 256>>>(x);

    cudaFuncSetAttribute(k_conv, cudaFuncAttributeMaxDynamicSharedMemorySize, SMEM_BYTES);
    dim3 grid(2, RES / 2, BATCH);
    k_conv<<<grid, 256, SMEM_BYTES>>>(noise, nstr, bias, out);
}